// round 15
// baseline (speedup 1.0000x reference)
#include <cuda_runtime.h>
#include <math.h>
#include <stdint.h>

#define NV 20
#define NC 128
#define NT 64
#define NH 192
#define N_TL 9
#define N_LT 20
#define NDEPTH 3

#define NTHR 512
#define PA  136   // activation pitch (floats): conflict-free mma fragments
#define PWT 68    // transposed token-weight pitch

// shared layout (floats) — wt* and wc* share one union region (disjoint in time)
#define OFF_SF   0        // f state [64][136]
#define OFF_SY   8704     // scratch  [64][136]
#define OFF_WU   17408    // union: {wt0,wt1 [64][68]} OR {wc0,wc1 [32][136]}
#define OFF_SG   26112    // 96
#define OFF_SRED 26208    // 16
#define OFF_SIDX 26224    // 64 ints
#define SMEM_FLOATS 26288
#define SMEM_BYTES (SMEM_FLOATS*4)

struct Params {
  const float* x;
  const float* tl_table; const float* lane_table;
  const float* ch1w; const float* ch1b; const float* ch2w; const float* ch2b;
  const float* tk1w; const float* tk1b; const float* tk2w; const float* tk2b;
  const float* bn1w; const float* bn1b;
  const float* bt1w; const float* bt1b; const float* bt2w; const float* bt2b;
  const float* bn2w; const float* bn2b;
  const float* bc1w; const float* bc1b; const float* bc2w; const float* bc2b;
  const float* nw;  const float* nb;
  const float* e1w; const float* e1b; const float* e2w; const float* e2b;
  float* out; float* mask_out; float* pos_out;
};

__device__ __forceinline__ float gelu_f(float v){
  return 0.5f * v * (1.0f + erff(v * 0.70710678118654752440f));
}
__device__ __forceinline__ uint32_t tf32r(float x){
  uint32_t r; asm("cvt.rna.tf32.f32 %0, %1;" : "=r"(r) : "f"(x)); return r;
}
__device__ __forceinline__ float tf32f(float x){ return __uint_as_float(tf32r(x)); }

__device__ __forceinline__ void mma8(float d[4], uint32_t a0, uint32_t a1,
                                     uint32_t a2, uint32_t a3,
                                     uint32_t b0, uint32_t b1){
  asm volatile("mma.sync.aligned.m16n8k8.row.col.f32.tf32.tf32.f32 "
               "{%0,%1,%2,%3}, {%4,%5,%6,%7}, {%8,%9}, {%0,%1,%2,%3};"
               : "+f"(d[0]), "+f"(d[1]), "+f"(d[2]), "+f"(d[3])
               : "r"(a0), "r"(a1), "r"(a2), "r"(a3), "r"(b0), "r"(b1));
}

__device__ __forceinline__ void zacc(float acc[4][4]){
  #pragma unroll
  for (int j = 0; j < 4; j++)
    #pragma unroll
    for (int q = 0; q < 4; q++) acc[j][q] = 0.f;
}

// ---- channel-type GEMM, one staged 32-k tile (one m16 tile per warp) -------
__device__ __forceinline__ void chan_tile_mma(const float* Act, const float* Wc,
                                              float acc[4][4], int mbase, int nbase,
                                              int k0, int g, int tg, bool active){
  if (!active) return;
  #pragma unroll
  for (int kk = 0; kk < 32; kk += 8){
    const float* ap = Act + (mbase + g)*PA + k0 + kk + tg;
    uint32_t a0 = __float_as_uint(ap[0]);
    uint32_t a1 = __float_as_uint(ap[8*PA]);
    uint32_t a2 = __float_as_uint(ap[4]);
    uint32_t a3 = __float_as_uint(ap[8*PA + 4]);
    const float* bp = Wc + (kk + tg)*PA + nbase + g;
    #pragma unroll
    for (int j = 0; j < 4; j++){
      uint32_t b0 = __float_as_uint(bp[8*j]);
      uint32_t b1 = __float_as_uint(bp[4*PA + 8*j]);
      mma8(acc[j], a0, a1, a2, a3, b0, b1);
    }
  }
}

// stage one 32x128 weight tile: gmem -> regs -> smem (tf32-rounded), 512 thr
__device__ __forceinline__ void ldg_wc(float4 pre[2], const float* __restrict__ src, int tid){
  const float4* g4 = reinterpret_cast<const float4*>(src);
  #pragma unroll
  for (int q = 0; q < 2; q++) pre[q] = g4[tid + NTHR*q];
}
__device__ __forceinline__ void sts_wc(const float4 pre[2], float* wc, int tid){
  #pragma unroll
  for (int q = 0; q < 2; q++){
    int idx = tid + NTHR*q;
    int row = idx >> 5;
    int col = (idx & 31) * 4;
    float4 v;
    v.x = __uint_as_float(tf32r(pre[q].x));
    v.y = __uint_as_float(tf32r(pre[q].y));
    v.z = __uint_as_float(tf32r(pre[q].z));
    v.w = __uint_as_float(tf32r(pre[q].w));
    *reinterpret_cast<float4*>(wc + row*PA + col) = v;
  }
}

// full K=128 chan GEMM; precondition: tile0 in wc0 + synced.
// postcondition: if WgNext, its tile0 sits in wc0 (synced).
__device__ void chan_gemm(const float* Act, const float* __restrict__ Wg,
                          const float* __restrict__ WgNext,
                          float acc[4][4], float* wc0, float* wc1,
                          int mbase, int nbase, int g, int tg, int tid, bool active){
  float4 pre[2];
  #pragma unroll
  for (int t = 0; t < 4; t++){
    const float* nsrc = (t < 3) ? (Wg + (t+1)*32*NC) : WgNext;
    if (nsrc) ldg_wc(pre, nsrc, tid);
    chan_tile_mma(Act, (t & 1) ? wc1 : wc0, acc, mbase, nbase, t*32, g, tg, active);
    if (nsrc) sts_wc(pre, (t & 1) ? wc0 : wc1, tid);
    __syncthreads();
  }
}

// ---- token-type GEMM: out[u][c] = sum_t wT[u][t] * Act[t][c] ---------------
template<int K8>
__device__ __forceinline__ void tok_mma(const float* Act, const float* wT,
                                        float acc[4][4], int mbase, int nbase,
                                        int g, int tg){
  #pragma unroll
  for (int ks = 0; ks < K8; ks++){
    const float* ap = wT + (mbase + g)*PWT + 8*ks + tg;
    uint32_t a0 = __float_as_uint(ap[0]);
    uint32_t a1 = __float_as_uint(ap[8*PWT]);
    uint32_t a2 = __float_as_uint(ap[4]);
    uint32_t a3 = __float_as_uint(ap[8*PWT + 4]);
    const float* bp = Act + (8*ks + tg)*PA + nbase + g;
    #pragma unroll
    for (int j = 0; j < 4; j++){
      uint32_t b0 = __float_as_uint(bp[8*j]);
      uint32_t b1 = __float_as_uint(bp[4*PA + 8*j]);
      mma8(acc[j], a0, a1, a2, a3, b0, b1);
    }
  }
}

// stage token weight transposed + rounded: g[Krows][64] -> wT[64][PWT]
__device__ void stage_wt(float* wT, const float* __restrict__ gsrc,
                         int Krows, int Kpad, int tid){
  for (int idx = tid; idx < Kpad*64; idx += NTHR){
    int t = idx >> 6, u = idx & 63;
    float v = (t < Krows) ? gsrc[idx] : 0.f;
    wT[u*PWT + t] = __uint_as_float(tf32r(v));
  }
}

// LN of one row; rounded (tf32) store
__device__ __forceinline__ void ln_row(const float* srow, float* drow,
                                       const float wg[4], const float bg[4], int lane){
  float v[4]; float s = 0.f, q = 0.f;
  #pragma unroll
  for (int j = 0; j < 4; j++){
    v[j] = srow[lane + 32*j];
    s += v[j]; q += v[j]*v[j];
  }
  #pragma unroll
  for (int o = 16; o > 0; o >>= 1){
    s += __shfl_xor_sync(0xffffffffu, s, o);
    q += __shfl_xor_sync(0xffffffffu, q, o);
  }
  float m   = s * (1.f/NC);
  float var = q * (1.f/NC) - m*m;
  float rs  = rsqrtf(var + 1e-5f);
  #pragma unroll
  for (int j = 0; j < 4; j++)
    drow[lane + 32*j] = tf32f((v[j]-m)*rs*wg[j] + bg[j]);
}

__global__ void __launch_bounds__(NTHR, 2)
lane_fusion_kernel(Params P){
  extern __shared__ float smem[];
  float* sf  = smem + OFF_SF;
  float* sy  = smem + OFF_SY;
  float* wt0 = smem + OFF_WU;
  float* wt1 = smem + OFF_WU + 4352;
  float* wc0 = smem + OFF_WU;
  float* wc1 = smem + OFF_WU + 4352;
  float* sg  = smem + OFF_SG;
  float* sred= smem + OFF_SRED;
  int*   sidx= (int*)(smem + OFF_SIDX);

  const int tid  = threadIdx.x;
  const int lane = tid & 31;
  const int warp = tid >> 5;          // 0..15
  const int g_   = lane >> 2;
  const int tg   = lane & 3;
  const int mbase = (warp & 3) * 16;  // 4 m-tiles
  const int nbase = (warp >> 2) * 32; // 4 n-ranges
  const int r    = blockIdx.x;
  const float* xr = P.x + (size_t)r * (NV*5);

  // ----- preprocess -----
  if (tid < NV){
    float x0 = xr[tid*5+0], x1 = xr[tid*5+1], hg = xr[tid*5+2];
    float x3 = xr[tid*5+3], x4 = xr[tid*5+4];
    float ch = cosf(hg), sh = sinf(hg);
    sg[tid*4+0] = x0; sg[tid*4+1] = x1; sg[tid*4+2] = ch; sg[tid*4+3] = sh;
    int tl = (int)x3; tl = tl < 0 ? 0 : (tl > N_TL-1 ? N_TL-1 : tl);
    int lt = (int)x4; lt = lt < 0 ? 0 : (lt > N_LT-1 ? N_LT-1 : lt);
    sidx[tid]      = tl;
    sidx[NV+tid]   = lt;
    sidx[2*NV+tid] = (x0==0.f && x1==0.f && ch==0.f && sh==0.f) ? 1 : 0;
  }
  if (tid < 5){
    float mid = xr[(NV/2)*5 + tid];
    float sc = (tid==3) ? (1.f/(N_TL-1)) : ((tid==4) ? (1.f/(N_LT-1)) : 1.f);
    P.pos_out[(size_t)r*5 + tid] = mid * sc;
  }
  __syncthreads();
  if (tid == 0){
    int mp = 1;
    for (int v = 0; v < NV; v++) mp &= sidx[2*NV+v];
    sidx[3*NV] = mp;
    P.mask_out[r] = mp ? 1.f : 0.f;
  }

  // ----- stage 1a: h1 = gelu(g @ ch1w + b) -> sy rows 0..19 (20..23 zero), tf32
  {
    int c  = tid & 127;
    int hf = tid >> 7;   // 0..3
    for (int v = hf; v < 24; v += 4){
      float o;
      if (v < NV){
        float a = P.ch1b[c]
                + sg[v*4+0]*P.ch1w[0*NC + c] + sg[v*4+1]*P.ch1w[1*NC + c]
                + sg[v*4+2]*P.ch1w[2*NC + c] + sg[v*4+3]*P.ch1w[3*NC + c];
        o = tf32f(gelu_f(a));
      } else o = 0.f;
      sy[v*PA + c] = o;
    }
  }
  // stage first ch2w tile into wc0 (union region: chan phase)
  {
    float4 pre[2];
    ldg_wc(pre, P.ch2w, tid);
    sts_wc(pre, wc0, tid);
  }
  __syncthreads();

  // ----- stage 1b: f0 = h1 @ ch2w + b + tables -> sf rows 0..19 (20..23 zero)
  {
    float acc[4][4]; zacc(acc);
    bool active = (mbase < 32);   // rows 0..31
    chan_gemm(sy, P.ch2w, nullptr, acc, wc0, wc1, mbase, nbase, g_, tg, tid, active);
    if (active){
      #pragma unroll
      for (int rr = 0; rr < 2; rr++){
        int v = mbase + g_ + rr*8;
        if (v < NV){
          int tl = sidx[v], lt = sidx[NV+v];
          #pragma unroll
          for (int j = 0; j < 4; j++){
            int cn = nbase + 8*j + 2*tg;
            float2 b2 = *reinterpret_cast<const float2*>(P.ch2b + cn);
            float2 t2 = *reinterpret_cast<const float2*>(P.tl_table + tl*NC + cn);
            float2 l2 = *reinterpret_cast<const float2*>(P.lane_table + lt*NC + cn);
            float2 o;
            o.x = tf32f(acc[j][rr*2+0] + b2.x + t2.x + l2.x);
            o.y = tf32f(acc[j][rr*2+1] + b2.y + t2.y + l2.y);
            *reinterpret_cast<float2*>(sf + v*PA + cn) = o;
          }
        } else if (v < 24){
          #pragma unroll
          for (int j = 0; j < 4; j++){
            int cn = nbase + 8*j + 2*tg;
            float2 z; z.x = 0.f; z.y = 0.f;
            *reinterpret_cast<float2*>(sf + v*PA + cn) = z;
          }
        }
      }
    }
  }
  __syncthreads();   // S1: f0 ready; wc reads done — union region free

  // stage token-expansion weights (union region: token phase)
  stage_wt(wt0, P.tk1w, NV, 24, tid);
  stage_wt(wt1, P.tk2w, NT, NT, tid);
  __syncthreads();   // S1b: wt ready

  // ----- token expansion: 20 -> 64 -----
  {
    float acc[4][4]; zacc(acc);
    tok_mma<3>(sf, wt0, acc, mbase, nbase, g_, tg);
    #pragma unroll
    for (int rr = 0; rr < 2; rr++){
      int u = mbase + g_ + rr*8;
      float bb = P.tk1b[u];
      #pragma unroll
      for (int j = 0; j < 4; j++){
        int cn = nbase + 8*j + 2*tg;
        float2 o;
        o.x = tf32f(gelu_f(acc[j][rr*2+0] + bb));
        o.y = tf32f(gelu_f(acc[j][rr*2+1] + bb));
        *reinterpret_cast<float2*>(sy + u*PA + cn) = o;
      }
    }
  }
  __syncthreads();   // S2: z1 ready
  {
    float acc[4][4]; zacc(acc);
    tok_mma<8>(sy, wt1, acc, mbase, nbase, g_, tg);
    #pragma unroll
    for (int rr = 0; rr < 2; rr++){
      int t = mbase + g_ + rr*8;
      float bb = P.tk2b[t];
      #pragma unroll
      for (int j = 0; j < 4; j++){
        int cn = nbase + 8*j + 2*tg;
        float2 o;
        o.x = acc[j][rr*2+0] + bb;
        o.y = acc[j][rr*2+1] + bb;
        *reinterpret_cast<float2*>(sf + t*PA + cn) = o;   // fp32 state
      }
    }
  }
  __syncthreads();   // S3: f ready

  // ----- mixer blocks -----
  for (int d = 0; d < NDEPTH; d++){
    // LN1 (4 rows/warp) -> sy ; stage this depth's token weights
    {
      float wg[4], bg[4];
      #pragma unroll
      for (int j = 0; j < 4; j++){
        wg[j] = P.bn1w[d*NC + lane + 32*j];
        bg[j] = P.bn1b[d*NC + lane + 32*j];
      }
      #pragma unroll
      for (int i = 0; i < 4; i++){
        int t = warp*4 + i;
        ln_row(sf + t*PA, sy + t*PA, wg, bg, lane);
      }
      stage_wt(wt0, P.bt1w + d*NT*NT, NT, NT, tid);
      stage_wt(wt1, P.bt2w + d*NT*NT, NT, NT, tid);
    }
    __syncthreads();   // A

    // token mix 1
    {
      float acc[4][4]; zacc(acc);
      tok_mma<8>(sy, wt0, acc, mbase, nbase, g_, tg);
      __syncthreads(); // B
      #pragma unroll
      for (int rr = 0; rr < 2; rr++){
        int u = mbase + g_ + rr*8;
        float bb = P.bt1b[d*NT + u];
        #pragma unroll
        for (int j = 0; j < 4; j++){
          int cn = nbase + 8*j + 2*tg;
          float2 o;
          o.x = tf32f(gelu_f(acc[j][rr*2+0] + bb));
          o.y = tf32f(gelu_f(acc[j][rr*2+1] + bb));
          *reinterpret_cast<float2*>(sy + u*PA + cn) = o;
        }
      }
    }
    __syncthreads();   // C

    // token mix 2 + residual
    {
      float acc[4][4]; zacc(acc);
      tok_mma<8>(sy, wt1, acc, mbase, nbase, g_, tg);
      #pragma unroll
      for (int rr = 0; rr < 2; rr++){
        int t = mbase + g_ + rr*8;
        float bb = P.bt2b[d*NT + t];
        #pragma unroll
        for (int j = 0; j < 4; j++){
          int cn = nbase + 8*j + 2*tg;
          float2 o = *reinterpret_cast<float2*>(sf + t*PA + cn);
          o.x += acc[j][rr*2+0] + bb;
          o.y += acc[j][rr*2+1] + bb;
          *reinterpret_cast<float2*>(sf + t*PA + cn) = o;
        }
      }
    }
    __syncthreads();   // D: all wt reads done — union region free

    // LN2 -> sy ; stage bc1w tile0 -> wc0 (union region: chan phase)
    {
      float wg[4], bg[4];
      #pragma unroll
      for (int j = 0; j < 4; j++){
        wg[j] = P.bn2w[d*NC + lane + 32*j];
        bg[j] = P.bn2b[d*NC + lane + 32*j];
      }
      #pragma unroll
      for (int i = 0; i < 4; i++){
        int t = warp*4 + i;
        ln_row(sf + t*PA, sy + t*PA, wg, bg, lane);
      }
      float4 pre[2];
      ldg_wc(pre, P.bc1w + d*NC*NC, tid);
      sts_wc(pre, wc0, tid);
    }
    __syncthreads();   // E

    // channel mix C1: h = gelu(y2 @ Wc1 + b1) -> sy (tf32)
    {
      float acc[4][4]; zacc(acc);
      chan_gemm(sy, P.bc1w + d*NC*NC, P.bc2w + d*NC*NC, acc, wc0, wc1,
                mbase, nbase, g_, tg, tid, true);
      #pragma unroll
      for (int j = 0; j < 4; j++){
        int cn = nbase + 8*j + 2*tg;
        float2 b2 = *reinterpret_cast<const float2*>(P.bc1b + d*NC + cn);
        #pragma unroll
        for (int rr = 0; rr < 2; rr++){
          int t = mbase + g_ + rr*8;
          float2 o;
          o.x = tf32f(gelu_f(acc[j][rr*2+0] + b2.x));
          o.y = tf32f(gelu_f(acc[j][rr*2+1] + b2.y));
          *reinterpret_cast<float2*>(sy + t*PA + cn) = o;
        }
      }
    }
    __syncthreads();   // G: h ready

    // channel mix C2: f += h @ Wc2 + b2
    {
      float acc[4][4]; zacc(acc);
      chan_gemm(sy, P.bc2w + d*NC*NC, nullptr, acc, wc0, wc1,
                mbase, nbase, g_, tg, tid, true);
      #pragma unroll
      for (int j = 0; j < 4; j++){
        int cn = nbase + 8*j + 2*tg;
        float2 b2 = *reinterpret_cast<const float2*>(P.bc2b + d*NC + cn);
        #pragma unroll
        for (int rr = 0; rr < 2; rr++){
          int t = mbase + g_ + rr*8;
          float2 o = *reinterpret_cast<float2*>(sf + t*PA + cn);
          o.x += acc[j][rr*2+0] + b2.x;
          o.y += acc[j][rr*2+1] + b2.y;
          *reinterpret_cast<float2*>(sf + t*PA + cn) = o;
        }
      }
    }
    __syncthreads();   // H: sf complete; union region free
  }

  // ----- epilogue: token mean, LN, emb MLP (scalar fp32) -----
  {
    int c  = tid & 127;
    int hf = tid >> 7;   // 0..3
    float ps = 0.f;
    #pragma unroll 4
    for (int t = hf*16; t < hf*16 + 16; t++) ps += sf[t*PA + c];
    sy[hf*128 + c] = ps;
  }
  __syncthreads();
  float fm = 0.f;
  if (tid < NC){
    fm = (sy[tid] + sy[128 + tid] + sy[256 + tid] + sy[384 + tid]) * (1.f/NT);
    float s = fm, q = fm*fm;
    #pragma unroll
    for (int o = 16; o > 0; o >>= 1){
      s += __shfl_xor_sync(0xffffffffu, s, o);
      q += __shfl_xor_sync(0xffffffffu, q, o);
    }
    if (lane == 0){ sred[warp] = s; sred[4+warp] = q; }
  }
  __syncthreads();
  if (tid < NC){
    float s = sred[0]+sred[1]+sred[2]+sred[3];
    float q = sred[4]+sred[5]+sred[6]+sred[7];
    float m  = s * (1.f/NC);
    float var = q * (1.f/NC) - m*m;
    float rs = rsqrtf(var + 1e-5f);
    sy[512 + tid] = (fm - m)*rs*P.nw[tid] + P.nb[tid];
  }
  __syncthreads();
  if (tid < NH){
    float a = P.e1b[tid];
    #pragma unroll 8
    for (int c = 0; c < NC; c++) a += sy[512 + c] * P.e1w[c*NH + tid];
    sy[768 + tid] = gelu_f(a);
  }
  __syncthreads();
  if (tid < NH){
    float o = P.e2b[tid];
    #pragma unroll 8
    for (int j = 0; j < NH; j++) o += sy[768 + j] * P.e2w[j*NH + tid];
    float valid = sidx[3*NV] ? 0.f : 1.f;
    P.out[(size_t)r * NH + tid] = o * valid;
  }
}

extern "C" void kernel_launch(void* const* d_in, const int* in_sizes, int n_in,
                              void* d_out, int out_size){
  (void)in_sizes; (void)n_in; (void)out_size;
  Params P;
  P.x         = (const float*)d_in[0];
  P.tl_table  = (const float*)d_in[1];
  P.lane_table= (const float*)d_in[2];
  P.ch1w = (const float*)d_in[3];  P.ch1b = (const float*)d_in[4];
  P.ch2w = (const float*)d_in[5];  P.ch2b = (const float*)d_in[6];
  P.tk1w = (const float*)d_in[7];  P.tk1b = (const float*)d_in[8];
  P.tk2w = (const float*)d_in[9];  P.tk2b = (const float*)d_in[10];
  P.bn1w = (const float*)d_in[11]; P.bn1b = (const float*)d_in[12];
  P.bt1w = (const float*)d_in[13]; P.bt1b = (const float*)d_in[14];
  P.bt2w = (const float*)d_in[15]; P.bt2b = (const float*)d_in[16];
  P.bn2w = (const float*)d_in[17]; P.bn2b = (const float*)d_in[18];
  P.bc1w = (const float*)d_in[19]; P.bc1b = (const float*)d_in[20];
  P.bc2w = (const float*)d_in[21]; P.bc2b = (const float*)d_in[22];
  P.nw   = (const float*)d_in[23]; P.nb   = (const float*)d_in[24];
  P.e1w  = (const float*)d_in[25]; P.e1b  = (const float*)d_in[26];
  P.e2w  = (const float*)d_in[27]; P.e2b  = (const float*)d_in[28];

  const int NRows = 8192;
  float* ob = (float*)d_out;
  P.out      = ob;
  P.mask_out = ob + (size_t)NRows*NH;
  P.pos_out  = ob + (size_t)NRows*NH + NRows;

  cudaFuncSetAttribute(lane_fusion_kernel,
                       cudaFuncAttributeMaxDynamicSharedMemorySize, SMEM_BYTES);
  lane_fusion_kernel<<<NRows, NTHR, SMEM_BYTES>>>(P);
}

// round 16
// speedup vs baseline: 1.1894x; 1.1894x over previous
#include <cuda_runtime.h>
#include <math.h>
#include <stdint.h>

#define NV 20
#define NC 128
#define NT 64
#define NH 192
#define N_TL 9
#define N_LT 20
#define NDEPTH 3

#define PA  136   // activation pitch
#define PWT 68    // transposed token-weight pitch

// shared layout (floats)
#define OFF_ACT  0        // activation buffer [64][136]
#define OFF_WU   8704     // union: {wt0,wt1 [64][68]} OR {wc0,wc1 [32][136]}
#define OFF_SG   17408    // 96
#define OFF_SRED 17504    // 512 : LN partials [64][8] (s[4]|q[4])
#define OFF_SIDX 18016    // 64 ints
#define SMEM_FLOATS 18080
#define SMEM_BYTES (SMEM_FLOATS*4)

struct Params {
  const float* x;
  const float* tl_table; const float* lane_table;
  const float* ch1w; const float* ch1b; const float* ch2w; const float* ch2b;
  const float* tk1w; const float* tk1b; const float* tk2w; const float* tk2b;
  const float* bn1w; const float* bn1b;
  const float* bt1w; const float* bt1b; const float* bt2w; const float* bt2b;
  const float* bn2w; const float* bn2b;
  const float* bc1w; const float* bc1b; const float* bc2w; const float* bc2b;
  const float* nw;  const float* nb;
  const float* e1w; const float* e1b; const float* e2w; const float* e2b;
  float* out; float* mask_out; float* pos_out;
};

__device__ __forceinline__ float gelu_f(float v){
  return 0.5f * v * (1.0f + erff(v * 0.70710678118654752440f));
}
__device__ __forceinline__ uint32_t tf32r(float x){
  uint32_t r; asm("cvt.rna.tf32.f32 %0, %1;" : "=r"(r) : "f"(x)); return r;
}
__device__ __forceinline__ float tf32f(float x){ return __uint_as_float(tf32r(x)); }

__device__ __forceinline__ void mma8(float d[4], uint32_t a0, uint32_t a1,
                                     uint32_t a2, uint32_t a3,
                                     uint32_t b0, uint32_t b1){
  asm volatile("mma.sync.aligned.m16n8k8.row.col.f32.tf32.tf32.f32 "
               "{%0,%1,%2,%3}, {%4,%5,%6,%7}, {%8,%9}, {%0,%1,%2,%3};"
               : "+f"(d[0]), "+f"(d[1]), "+f"(d[2]), "+f"(d[3])
               : "r"(a0), "r"(a1), "r"(a2), "r"(a3), "r"(b0), "r"(b1));
}

__device__ __forceinline__ void zacc(float acc[2][4][4]){
  #pragma unroll
  for (int m = 0; m < 2; m++)
    #pragma unroll
    for (int j = 0; j < 4; j++)
      #pragma unroll
      for (int q = 0; q < 4; q++) acc[m][j][q] = 0.f;
}

// ---- cp.async staging of a 32x128 chan weight tile (raw fp32 bits) ---------
__device__ __forceinline__ void cpa_tile(float* wc, const float* __restrict__ src, int tid){
  #pragma unroll
  for (int q = 0; q < 4; q++){
    int idx = tid + 256*q;
    int row = idx >> 5, c4 = idx & 31;
    uint32_t sa = (uint32_t)__cvta_generic_to_shared(wc + row*PA + c4*4);
    asm volatile("cp.async.ca.shared.global [%0], [%1], 16;"
                 :: "r"(sa), "l"(src + row*NC + c4*4) : "memory");
  }
  asm volatile("cp.async.commit_group;" ::: "memory");
}
__device__ __forceinline__ void cpa_wait(){
  asm volatile("cp.async.wait_group 0;" ::: "memory");
}

// ---- channel-type GEMM tile; B (weights) tf32-rounded AT READ --------------
__device__ __forceinline__ void chan_tile_mma(const float* Act, const float* Wc,
                                              float acc[2][4][4], int mbase, int nbase,
                                              int k0, int g, int tg, bool active){
  if (!active) return;
  #pragma unroll
  for (int kk = 0; kk < 32; kk += 8){
    uint32_t af[2][4];
    #pragma unroll
    for (int mi = 0; mi < 2; mi++){
      const float* ap = Act + (mbase + mi*16 + g)*PA + k0 + kk + tg;
      af[mi][0] = __float_as_uint(ap[0]);
      af[mi][1] = __float_as_uint(ap[8*PA]);
      af[mi][2] = __float_as_uint(ap[4]);
      af[mi][3] = __float_as_uint(ap[8*PA + 4]);
    }
    const float* bp = Wc + (kk + tg)*PA + nbase + g;
    #pragma unroll
    for (int j = 0; j < 4; j++){
      uint32_t b0 = tf32r(bp[8*j]);          // rna at read == rna at stage
      uint32_t b1 = tf32r(bp[4*PA + 8*j]);
      #pragma unroll
      for (int mi = 0; mi < 2; mi++)
        mma8(acc[mi][j], af[mi][0], af[mi][1], af[mi][2], af[mi][3], b0, b1);
    }
  }
}

// full K=128 chan GEMM, cp.async ping-pong. precondition: tile0 in wc0 + synced.
// postcondition: if WgNext, its tile0 sits in wc0 (synced).
template<bool FINAL_SYNC>
__device__ void chan_gemm(const float* Act, const float* __restrict__ Wg,
                          const float* __restrict__ WgNext,
                          float acc[2][4][4], float* wc0, float* wc1,
                          int mbase, int nbase, int g, int tg, int tid, bool active){
  #pragma unroll
  for (int t = 0; t < 4; t++){
    const float* nsrc = (t < 3) ? (Wg + (t+1)*32*NC) : WgNext;
    if (nsrc) cpa_tile((t & 1) ? wc0 : wc1, nsrc, tid);
    chan_tile_mma(Act, (t & 1) ? wc1 : wc0, acc, mbase, nbase, t*32, g, tg, active);
    if (nsrc) cpa_wait();
    if (t < 3 || FINAL_SYNC) __syncthreads();
  }
}

// ---- token-type GEMM: out[u][c] = sum_t wT[u][t] * Act[t][c] ---------------
template<int K8>
__device__ __forceinline__ void tok_mma(const float* Act, const float* wT,
                                        float acc[2][4][4], int mbase, int nbase,
                                        int g, int tg){
  #pragma unroll
  for (int ks = 0; ks < K8; ks++){
    uint32_t af[2][4];
    #pragma unroll
    for (int mi = 0; mi < 2; mi++){
      const float* ap = wT + (mbase + mi*16 + g)*PWT + 8*ks + tg;
      af[mi][0] = __float_as_uint(ap[0]);
      af[mi][1] = __float_as_uint(ap[8*PWT]);
      af[mi][2] = __float_as_uint(ap[4]);
      af[mi][3] = __float_as_uint(ap[8*PWT + 4]);
    }
    const float* bp = Act + (8*ks + tg)*PA + nbase + g;
    #pragma unroll
    for (int j = 0; j < 4; j++){
      uint32_t b0 = __float_as_uint(bp[8*j]);
      uint32_t b1 = __float_as_uint(bp[4*PA + 8*j]);
      #pragma unroll
      for (int mi = 0; mi < 2; mi++)
        mma8(acc[mi][j], af[mi][0], af[mi][1], af[mi][2], af[mi][3], b0, b1);
    }
  }
}

// stage token weight transposed + rounded: g[Krows][64] -> wT[64][PWT]
__device__ void stage_wt(float* wT, const float* __restrict__ gsrc,
                         int Krows, int Kpad, int tid){
  for (int idx = tid; idx < Kpad*64; idx += 256){
    int t = idx >> 6, u = idx & 63;
    float v = (t < Krows) ? gsrc[idx] : 0.f;
    wT[u*PWT + t] = __uint_as_float(tf32r(v));
  }
}

// ---- LayerNorm from register-resident f ------------------------------------
__device__ __forceinline__ void ln_partials(const float ff[2][4][4], float* sred,
                                            int mbase, int nb, int g_, int tg){
  #pragma unroll
  for (int mi = 0; mi < 2; mi++)
    #pragma unroll
    for (int rr = 0; rr < 2; rr++){
      float s = 0.f, q = 0.f;
      #pragma unroll
      for (int j = 0; j < 4; j++){
        float v0 = ff[mi][j][rr*2+0], v1 = ff[mi][j][rr*2+1];
        s += v0 + v1; q += v0*v0 + v1*v1;
      }
      s += __shfl_xor_sync(0xffffffffu, s, 1);
      s += __shfl_xor_sync(0xffffffffu, s, 2);
      q += __shfl_xor_sync(0xffffffffu, q, 1);
      q += __shfl_xor_sync(0xffffffffu, q, 2);
      if (tg == 0){
        int row = mbase + mi*16 + g_ + rr*8;
        sred[row*8 + nb]     = s;
        sred[row*8 + 4 + nb] = q;
      }
    }
}
__device__ __forceinline__ void ln_finish(const float ff[2][4][4], const float* sred,
                                          float* act, const float* __restrict__ wg_g,
                                          const float* __restrict__ bg_g,
                                          int mbase, int nbase, int g_, int tg){
  float2 wj[4], bj[4];
  #pragma unroll
  for (int j = 0; j < 4; j++){
    wj[j] = *reinterpret_cast<const float2*>(wg_g + nbase + 8*j + 2*tg);
    bj[j] = *reinterpret_cast<const float2*>(bg_g + nbase + 8*j + 2*tg);
  }
  #pragma unroll
  for (int mi = 0; mi < 2; mi++)
    #pragma unroll
    for (int rr = 0; rr < 2; rr++){
      int row = mbase + mi*16 + g_ + rr*8;
      float4 s4 = *reinterpret_cast<const float4*>(sred + row*8);
      float4 q4 = *reinterpret_cast<const float4*>(sred + row*8 + 4);
      float s = (s4.x + s4.y) + (s4.z + s4.w);
      float q = (q4.x + q4.y) + (q4.z + q4.w);
      float m   = s * (1.f/NC);
      float var = q * (1.f/NC) - m*m;
      float rs  = rsqrtf(var + 1e-5f);
      #pragma unroll
      for (int j = 0; j < 4; j++){
        float2 o;
        o.x = tf32f((ff[mi][j][rr*2+0]-m)*rs*wj[j].x + bj[j].x);
        o.y = tf32f((ff[mi][j][rr*2+1]-m)*rs*wj[j].y + bj[j].y);
        *reinterpret_cast<float2*>(act + row*PA + nbase + 8*j + 2*tg) = o;
      }
    }
}

__global__ void __launch_bounds__(256, 3)
lane_fusion_kernel(Params P){
  extern __shared__ float smem[];
  float* act = smem + OFF_ACT;
  float* wt0 = smem + OFF_WU;
  float* wt1 = smem + OFF_WU + 4352;
  float* wc0 = smem + OFF_WU;
  float* wc1 = smem + OFF_WU + 4352;
  float* sg  = smem + OFF_SG;
  float* sred= smem + OFF_SRED;
  int*   sidx= (int*)(smem + OFF_SIDX);

  const int tid  = threadIdx.x;
  const int lane = tid & 31;
  const int warp = tid >> 5;
  const int g_   = lane >> 2;
  const int tg   = lane & 3;
  const int mbase = (warp & 1) * 32;
  const int nbase = (warp >> 1) * 32;
  const int nb    = warp >> 1;
  const int r    = blockIdx.x;
  const float* xr = P.x + (size_t)r * (NV*5);

  // ----- preprocess -----
  if (tid < NV){
    float x0 = xr[tid*5+0], x1 = xr[tid*5+1], hg = xr[tid*5+2];
    float x3 = xr[tid*5+3], x4 = xr[tid*5+4];
    float ch = cosf(hg), sh = sinf(hg);
    sg[tid*4+0] = x0; sg[tid*4+1] = x1; sg[tid*4+2] = ch; sg[tid*4+3] = sh;
    int tl = (int)x3; tl = tl < 0 ? 0 : (tl > N_TL-1 ? N_TL-1 : tl);
    int lt = (int)x4; lt = lt < 0 ? 0 : (lt > N_LT-1 ? N_LT-1 : lt);
    sidx[tid]      = tl;
    sidx[NV+tid]   = lt;
    sidx[2*NV+tid] = (x0==0.f && x1==0.f && ch==0.f && sh==0.f) ? 1 : 0;
  }
  if (tid < 5){
    float mid = xr[(NV/2)*5 + tid];
    float sc = (tid==3) ? (1.f/(N_TL-1)) : ((tid==4) ? (1.f/(N_LT-1)) : 1.f);
    P.pos_out[(size_t)r*5 + tid] = mid * sc;
  }
  __syncthreads();
  if (tid == 0){
    int mp = 1;
    for (int v = 0; v < NV; v++) mp &= sidx[2*NV+v];
    sidx[3*NV] = mp;
    P.mask_out[r] = mp ? 1.f : 0.f;
  }

  // ----- 1a: h1 = gelu(g @ ch1w + b) -> act rows 0..23 (20..23 zero), tf32
  {
    int c  = tid & 127;
    int hf = tid >> 7;
    float w0 = P.ch1w[0*NC + c], w1 = P.ch1w[1*NC + c];
    float w2 = P.ch1w[2*NC + c], w3 = P.ch1w[3*NC + c];
    float b  = P.ch1b[c];
    #pragma unroll
    for (int v = hf*10; v < hf*10 + 10; v++){
      float a = b + sg[v*4+0]*w0 + sg[v*4+1]*w1 + sg[v*4+2]*w2 + sg[v*4+3]*w3;
      act[v*PA + c] = tf32f(gelu_f(a));
    }
    if (hf == 0){
      #pragma unroll
      for (int v = NV; v < 24; v++) act[v*PA + c] = 0.f;
    }
  }
  cpa_tile(wc0, P.ch2w, tid);   // ch2w tile0
  cpa_wait();
  __syncthreads();

  float ff[2][4][4];            // register-resident residual state tile

  // ----- 1b: f0 = h1 @ ch2w + b + tables -> act rows 32..55 (52..55 zero)
  {
    float acc[2][4][4]; zacc(acc);
    bool active = (mbase == 0);
    chan_gemm<true>(act, P.ch2w, nullptr, acc, wc0, wc1, mbase, nbase, g_, tg, tid, active);
    if (active){
      #pragma unroll
      for (int mi = 0; mi < 2; mi++)
        #pragma unroll
        for (int rr = 0; rr < 2; rr++){
          int v = mi*16 + g_ + rr*8;
          if (v < NV){
            int tl = sidx[v], lt = sidx[NV+v];
            #pragma unroll
            for (int j = 0; j < 4; j++){
              int cn = nbase + 8*j + 2*tg;
              float2 b2 = *reinterpret_cast<const float2*>(P.ch2b + cn);
              float2 t2 = *reinterpret_cast<const float2*>(P.tl_table + tl*NC + cn);
              float2 l2 = *reinterpret_cast<const float2*>(P.lane_table + lt*NC + cn);
              float2 o;
              o.x = tf32f(acc[mi][j][rr*2+0] + b2.x + t2.x + l2.x);
              o.y = tf32f(acc[mi][j][rr*2+1] + b2.y + t2.y + l2.y);
              *reinterpret_cast<float2*>(act + (32+v)*PA + cn) = o;
            }
          } else if (v < 24){
            #pragma unroll
            for (int j = 0; j < 4; j++){
              int cn = nbase + 8*j + 2*tg;
              float2 z; z.x = 0.f; z.y = 0.f;
              *reinterpret_cast<float2*>(act + (32+v)*PA + cn) = z;
            }
          }
        }
    }
    // wu free after chan_gemm's final internal sync
    stage_wt(wt0, P.tk1w, NV, 24, tid);
    stage_wt(wt1, P.tk2w, NT, NT, tid);
  }
  __syncthreads();   // S1: f0 + wt ready

  // ----- token expansion -----
  {
    float acc[2][4][4]; zacc(acc);
    tok_mma<3>(act + 32*PA, wt0, acc, mbase, nbase, g_, tg);   // B = f0
    __syncthreads(); // T1: all f0 reads done
    #pragma unroll
    for (int mi = 0; mi < 2; mi++)
      #pragma unroll
      for (int rr = 0; rr < 2; rr++){
        int u = mbase + mi*16 + g_ + rr*8;
        float bb = P.tk1b[u];
        #pragma unroll
        for (int j = 0; j < 4; j++){
          int cn = nbase + 8*j + 2*tg;
          float2 o;
          o.x = tf32f(gelu_f(acc[mi][j][rr*2+0] + bb));
          o.y = tf32f(gelu_f(acc[mi][j][rr*2+1] + bb));
          *reinterpret_cast<float2*>(act + u*PA + cn) = o;     // z1
        }
      }
  }
  __syncthreads();   // T2: z1 ready
  {
    zacc(ff);
    tok_mma<8>(act, wt1, ff, mbase, nbase, g_, tg);            // f = z1 @ W2
    #pragma unroll
    for (int mi = 0; mi < 2; mi++)
      #pragma unroll
      for (int rr = 0; rr < 2; rr++){
        float bb = P.tk2b[mbase + mi*16 + g_ + rr*8];
        #pragma unroll
        for (int j = 0; j < 4; j++){
          ff[mi][j][rr*2+0] += bb;
          ff[mi][j][rr*2+1] += bb;
        }
      }
  }
  __syncthreads();   // T3: z1 reads done; act free

  // ----- mixer blocks -----
  for (int d = 0; d < NDEPTH; d++){
    // LN1 partials + stage token weights
    ln_partials(ff, sred, mbase, nb, g_, tg);
    stage_wt(wt0, P.bt1w + d*NT*NT, NT, NT, tid);
    stage_wt(wt1, P.bt2w + d*NT*NT, NT, NT, tid);
    __syncthreads();  // A1
    ln_finish(ff, sred, act, P.bn1w + d*NC, P.bn1b + d*NC, mbase, nbase, g_, tg);
    __syncthreads();  // A2: y ready

    // token mix 1
    {
      float acc[2][4][4]; zacc(acc);
      tok_mma<8>(act, wt0, acc, mbase, nbase, g_, tg);
      __syncthreads(); // B: y reads done
      #pragma unroll
      for (int mi = 0; mi < 2; mi++)
        #pragma unroll
        for (int rr = 0; rr < 2; rr++){
          int u = mbase + mi*16 + g_ + rr*8;
          float bb = P.bt1b[d*NT + u];
          #pragma unroll
          for (int j = 0; j < 4; j++){
            int cn = nbase + 8*j + 2*tg;
            float2 o;
            o.x = tf32f(gelu_f(acc[mi][j][rr*2+0] + bb));
            o.y = tf32f(gelu_f(acc[mi][j][rr*2+1] + bb));
            *reinterpret_cast<float2*>(act + u*PA + cn) = o;   // z
          }
        }
    }
    __syncthreads();  // C: z ready

    // token mix 2: accumulate directly into ff (residual free)
    tok_mma<8>(act, wt1, ff, mbase, nbase, g_, tg);
    #pragma unroll
    for (int mi = 0; mi < 2; mi++)
      #pragma unroll
      for (int rr = 0; rr < 2; rr++){
        float bb = P.bt2b[d*NT + mbase + mi*16 + g_ + rr*8];
        #pragma unroll
        for (int j = 0; j < 4; j++){
          ff[mi][j][rr*2+0] += bb;
          ff[mi][j][rr*2+1] += bb;
        }
      }
    __syncthreads();  // D: z reads done; act + wu free

    // LN2 partials + async prefetch bc1w tile0
    cpa_tile(wc0, P.bc1w + d*NC*NC, tid);
    ln_partials(ff, sred, mbase, nb, g_, tg);
    __syncthreads();  // E1
    ln_finish(ff, sred, act, P.bn2w + d*NC, P.bn2b + d*NC, mbase, nbase, g_, tg);
    cpa_wait();
    __syncthreads();  // E2: y2 + wc0 ready

    // channel mix C1 -> h
    {
      float acc[2][4][4]; zacc(acc);
      chan_gemm<true>(act, P.bc1w + d*NC*NC, P.bc2w + d*NC*NC, acc, wc0, wc1,
                      mbase, nbase, g_, tg, tid, true);
      #pragma unroll
      for (int j = 0; j < 4; j++){
        int cn = nbase + 8*j + 2*tg;
        float2 b2 = *reinterpret_cast<const float2*>(P.bc1b + d*NC + cn);
        #pragma unroll
        for (int mi = 0; mi < 2; mi++)
          #pragma unroll
          for (int rr = 0; rr < 2; rr++){
            int t = mbase + mi*16 + g_ + rr*8;
            float2 o;
            o.x = tf32f(gelu_f(acc[mi][j][rr*2+0] + b2.x));
            o.y = tf32f(gelu_f(acc[mi][j][rr*2+1] + b2.y));
            *reinterpret_cast<float2*>(act + t*PA + cn) = o;   // h
          }
      }
    }
    __syncthreads();  // G: h ready

    // channel mix C2: accumulate into ff
    chan_gemm<false>(act, P.bc2w + d*NC*NC, nullptr, ff, wc0, wc1,
                     mbase, nbase, g_, tg, tid, true);
    #pragma unroll
    for (int j = 0; j < 4; j++){
      int cn = nbase + 8*j + 2*tg;
      float2 b2 = *reinterpret_cast<const float2*>(P.bc2b + d*NC + cn);
      #pragma unroll
      for (int mi = 0; mi < 2; mi++)
        #pragma unroll
        for (int rr = 0; rr < 2; rr++){
          ff[mi][j][rr*2+0] += b2.x;
          ff[mi][j][rr*2+1] += b2.y;
        }
    }
    __syncthreads();  // H: h reads done; act/sred free
  }

  // ----- epilogue: token mean from ff, LN, emb MLP -----
  {
    float cs[4][2];
    #pragma unroll
    for (int j = 0; j < 4; j++)
      #pragma unroll
      for (int q = 0; q < 2; q++)
        cs[j][q] = (ff[0][j][q] + ff[0][j][2+q]) + (ff[1][j][q] + ff[1][j][2+q]);
    #pragma unroll
    for (int off = 4; off <= 16; off <<= 1)
      #pragma unroll
      for (int j = 0; j < 4; j++)
        #pragma unroll
        for (int q = 0; q < 2; q++)
          cs[j][q] += __shfl_xor_sync(0xffffffffu, cs[j][q], off);
    if (g_ == 0){
      #pragma unroll
      for (int j = 0; j < 4; j++){
        float2 o; o.x = cs[j][0]; o.y = cs[j][1];
        *reinterpret_cast<float2*>(act + (warp & 1)*128 + nbase + 8*j + 2*tg) = o;
      }
    }
  }
  __syncthreads();
  float fm = 0.f;
  if (tid < NC){
    fm = (act[tid] + act[128 + tid]) * (1.f/NT);
    float s = fm, q = fm*fm;
    #pragma unroll
    for (int o = 16; o > 0; o >>= 1){
      s += __shfl_xor_sync(0xffffffffu, s, o);
      q += __shfl_xor_sync(0xffffffffu, q, o);
    }
    if (lane == 0){ sred[warp] = s; sred[4+warp] = q; }
  }
  __syncthreads();
  if (tid < NC){
    float s = sred[0]+sred[1]+sred[2]+sred[3];
    float q = sred[4]+sred[5]+sred[6]+sred[7];
    float m  = s * (1.f/NC);
    float var = q * (1.f/NC) - m*m;
    float rs = rsqrtf(var + 1e-5f);
    act[256 + tid] = (fm - m)*rs*P.nw[tid] + P.nb[tid];
  }
  __syncthreads();
  if (tid < NH){
    float a = P.e1b[tid];
    #pragma unroll 8
    for (int c = 0; c < NC; c++) a += act[256 + c] * P.e1w[c*NH + tid];
    act[512 + tid] = gelu_f(a);
  }
  __syncthreads();
  if (tid < NH){
    float o = P.e2b[tid];
    #pragma unroll 8
    for (int j = 0; j < NH; j++) o += act[512 + j] * P.e2w[j*NH + tid];
    float valid = sidx[3*NV] ? 0.f : 1.f;
    P.out[(size_t)r * NH + tid] = o * valid;
  }
}

extern "C" void kernel_launch(void* const* d_in, const int* in_sizes, int n_in,
                              void* d_out, int out_size){
  (void)in_sizes; (void)n_in; (void)out_size;
  Params P;
  P.x         = (const float*)d_in[0];
  P.tl_table  = (const float*)d_in[1];
  P.lane_table= (const float*)d_in[2];
  P.ch1w = (const float*)d_in[3];  P.ch1b = (const float*)d_in[4];
  P.ch2w = (const float*)d_in[5];  P.ch2b = (const float*)d_in[6];
  P.tk1w = (const float*)d_in[7];  P.tk1b = (const float*)d_in[8];
  P.tk2w = (const float*)d_in[9];  P.tk2b = (const float*)d_in[10];
  P.bn1w = (const float*)d_in[11]; P.bn1b = (const float*)d_in[12];
  P.bt1w = (const float*)d_in[13]; P.bt1b = (const float*)d_in[14];
  P.bt2w = (const float*)d_in[15]; P.bt2b = (const float*)d_in[16];
  P.bn2w = (const float*)d_in[17]; P.bn2b = (const float*)d_in[18];
  P.bc1w = (const float*)d_in[19]; P.bc1b = (const float*)d_in[20];
  P.bc2w = (const float*)d_in[21]; P.bc2b = (const float*)d_in[22];
  P.nw   = (const float*)d_in[23]; P.nb   = (const float*)d_in[24];
  P.e1w  = (const float*)d_in[25]; P.e1b  = (const float*)d_in[26];
  P.e2w  = (const float*)d_in[27]; P.e2b  = (const float*)d_in[28];

  const int NRows = 8192;
  float* ob = (float*)d_out;
  P.out      = ob;
  P.mask_out = ob + (size_t)NRows*NH;
  P.pos_out  = ob + (size_t)NRows*NH + NRows;

  cudaFuncSetAttribute(lane_fusion_kernel,
                       cudaFuncAttributeMaxDynamicSharedMemorySize, SMEM_BYTES);
  lane_fusion_kernel<<<NRows, 256, SMEM_BYTES>>>(P);
}

// round 17
// speedup vs baseline: 1.2856x; 1.0809x over previous
#include <cuda_runtime.h>
#include <math.h>
#include <stdint.h>

#define NV 20
#define NC 128
#define NT 64
#define NH 192
#define N_TL 9
#define N_LT 20
#define NDEPTH 3

#define PA  136   // activation pitch
#define PWT 68    // transposed token-weight pitch

// shared layout (floats)
#define OFF_ACT  0        // activation buffer [64][136]
#define OFF_WU   8704     // union: {wt0,wt1 [64][68]} OR {wc0,wc1 [32][136]}
#define OFF_SG   17408    // 96
#define OFF_SRED 17504    // 512 : LN partials [64][8]
#define OFF_SIDX 18016    // 64 ints
#define SMEM_FLOATS 18080
#define SMEM_BYTES (SMEM_FLOATS*4)

struct Params {
  const float* x;
  const float* tl_table; const float* lane_table;
  const float* ch1w; const float* ch1b; const float* ch2w; const float* ch2b;
  const float* tk1w; const float* tk1b; const float* tk2w; const float* tk2b;
  const float* bn1w; const float* bn1b;
  const float* bt1w; const float* bt1b; const float* bt2w; const float* bt2b;
  const float* bn2w; const float* bn2b;
  const float* bc1w; const float* bc1b; const float* bc2w; const float* bc2b;
  const float* nw;  const float* nb;
  const float* e1w; const float* e1b; const float* e2w; const float* e2b;
  float* out; float* mask_out; float* pos_out;
};

// pre-rounded / pre-transposed weights (written by prep kernel each launch)
__device__ float g_wt[8][64*PWT];   // 0:tk1w 1:tk2w 2+d:bt1w[d] 5+d:bt2w[d]
__device__ float g_wc[7][NC*NC];    // 0:ch2w 1+d:bc1w[d] 4+d:bc2w[d]

__device__ __forceinline__ float gelu_f(float v){
  return 0.5f * v * (1.0f + erff(v * 0.70710678118654752440f));
}
__device__ __forceinline__ uint32_t tf32r(float x){
  uint32_t r; asm("cvt.rna.tf32.f32 %0, %1;" : "=r"(r) : "f"(x)); return r;
}
__device__ __forceinline__ float tf32f(float x){ return __uint_as_float(tf32r(x)); }

// ---------------- prep kernel: round + transpose weights once ---------------
#define PREP_TOK (8*64*PWT)
#define PREP_TOT (PREP_TOK + 7*NC*NC)
__global__ void prep_kernel(Params P){
  int idx = blockIdx.x*blockDim.x + threadIdx.x;
  if (idx < PREP_TOK){
    int b    = idx / (64*PWT);
    int rloc = idx % (64*PWT);
    int u = rloc / PWT, t = rloc % PWT;
    const float* src; int K;
    if (b == 0){ src = P.tk1w; K = NV; }
    else if (b == 1){ src = P.tk2w; K = NT; }
    else if (b <= 4){ src = P.bt1w + (b-2)*NT*NT; K = NT; }
    else { src = P.bt2w + (b-5)*NT*NT; K = NT; }
    float v = (t < K) ? src[t*64 + u] : 0.f;
    g_wt[b][u*PWT + t] = __uint_as_float(tf32r(v));
  } else if (idx < PREP_TOT){
    int j = idx - PREP_TOK;
    int b = j / (NC*NC), e = j % (NC*NC);
    const float* src = (b == 0) ? P.ch2w
                     : (b <= 3) ? P.bc1w + (b-1)*NC*NC
                                : P.bc2w + (b-4)*NC*NC;
    g_wc[b][e] = __uint_as_float(tf32r(src[e]));
  }
}

__device__ __forceinline__ void mma8(float d[4], uint32_t a0, uint32_t a1,
                                     uint32_t a2, uint32_t a3,
                                     uint32_t b0, uint32_t b1){
  asm volatile("mma.sync.aligned.m16n8k8.row.col.f32.tf32.tf32.f32 "
               "{%0,%1,%2,%3}, {%4,%5,%6,%7}, {%8,%9}, {%0,%1,%2,%3};"
               : "+f"(d[0]), "+f"(d[1]), "+f"(d[2]), "+f"(d[3])
               : "r"(a0), "r"(a1), "r"(a2), "r"(a3), "r"(b0), "r"(b1));
}

__device__ __forceinline__ void zacc(float acc[2][4][4]){
  #pragma unroll
  for (int m = 0; m < 2; m++)
    #pragma unroll
    for (int j = 0; j < 4; j++)
      #pragma unroll
      for (int q = 0; q < 4; q++) acc[m][j][q] = 0.f;
}

// ---- cp.async staging ------------------------------------------------------
__device__ __forceinline__ void cpa_tile(float* wc, const float* __restrict__ src, int tid){
  #pragma unroll
  for (int q = 0; q < 4; q++){
    int idx = tid + 256*q;
    int row = idx >> 5, c4 = idx & 31;
    uint32_t sa = (uint32_t)__cvta_generic_to_shared(wc + row*PA + c4*4);
    asm volatile("cp.async.ca.shared.global [%0], [%1], 16;"
                 :: "r"(sa), "l"(src + row*NC + c4*4) : "memory");
  }
  asm volatile("cp.async.commit_group;" ::: "memory");
}
__device__ __forceinline__ void cpa_wt(float* dst, const float* __restrict__ src, int tid){
  #pragma unroll
  for (int i = tid; i < (64*PWT)/4; i += 256){
    uint32_t sa = (uint32_t)__cvta_generic_to_shared(dst + i*4);
    asm volatile("cp.async.ca.shared.global [%0], [%1], 16;"
                 :: "r"(sa), "l"(src + i*4) : "memory");
  }
  asm volatile("cp.async.commit_group;" ::: "memory");
}
__device__ __forceinline__ void cpa_wait(){
  asm volatile("cp.async.wait_group 0;" ::: "memory");
}

// ---- channel-type GEMM tile (weights pre-rounded) --------------------------
__device__ __forceinline__ void chan_tile_mma(const float* Act, const float* Wc,
                                              float acc[2][4][4], int mbase, int nbase,
                                              int k0, int g, int tg, bool active){
  if (!active) return;
  #pragma unroll
  for (int kk = 0; kk < 32; kk += 8){
    uint32_t af[2][4];
    #pragma unroll
    for (int mi = 0; mi < 2; mi++){
      const float* ap = Act + (mbase + mi*16 + g)*PA + k0 + kk + tg;
      af[mi][0] = __float_as_uint(ap[0]);
      af[mi][1] = __float_as_uint(ap[8*PA]);
      af[mi][2] = __float_as_uint(ap[4]);
      af[mi][3] = __float_as_uint(ap[8*PA + 4]);
    }
    const float* bp = Wc + (kk + tg)*PA + nbase + g;
    #pragma unroll
    for (int j = 0; j < 4; j++){
      uint32_t b0 = __float_as_uint(bp[8*j]);
      uint32_t b1 = __float_as_uint(bp[4*PA + 8*j]);
      #pragma unroll
      for (int mi = 0; mi < 2; mi++)
        mma8(acc[mi][j], af[mi][0], af[mi][1], af[mi][2], af[mi][3], b0, b1);
    }
  }
}

// full K=128 chan GEMM, cp.async ping-pong. precondition: tile0 in wc0 + synced.
template<bool FINAL_SYNC>
__device__ void chan_gemm(const float* Act, const float* __restrict__ Wg,
                          const float* __restrict__ WgNext,
                          float acc[2][4][4], float* wc0, float* wc1,
                          int mbase, int nbase, int g, int tg, int tid, bool active){
  #pragma unroll
  for (int t = 0; t < 4; t++){
    const float* nsrc = (t < 3) ? (Wg + (t+1)*32*NC) : WgNext;
    if (nsrc) cpa_tile((t & 1) ? wc0 : wc1, nsrc, tid);
    chan_tile_mma(Act, (t & 1) ? wc1 : wc0, acc, mbase, nbase, t*32, g, tg, active);
    if (nsrc) cpa_wait();
    if (t < 3 || FINAL_SYNC) __syncthreads();
  }
}

// ---- token-type GEMM -------------------------------------------------------
template<int K8>
__device__ __forceinline__ void tok_mma(const float* Act, const float* wT,
                                        float acc[2][4][4], int mbase, int nbase,
                                        int g, int tg){
  #pragma unroll
  for (int ks = 0; ks < K8; ks++){
    uint32_t af[2][4];
    #pragma unroll
    for (int mi = 0; mi < 2; mi++){
      const float* ap = wT + (mbase + mi*16 + g)*PWT + 8*ks + tg;
      af[mi][0] = __float_as_uint(ap[0]);
      af[mi][1] = __float_as_uint(ap[8*PWT]);
      af[mi][2] = __float_as_uint(ap[4]);
      af[mi][3] = __float_as_uint(ap[8*PWT + 4]);
    }
    const float* bp = Act + (8*ks + tg)*PA + nbase + g;
    #pragma unroll
    for (int j = 0; j < 4; j++){
      uint32_t b0 = __float_as_uint(bp[8*j]);
      uint32_t b1 = __float_as_uint(bp[4*PA + 8*j]);
      #pragma unroll
      for (int mi = 0; mi < 2; mi++)
        mma8(acc[mi][j], af[mi][0], af[mi][1], af[mi][2], af[mi][3], b0, b1);
    }
  }
}

// ---- LayerNorm from register-resident f ------------------------------------
__device__ __forceinline__ void ln_partials(const float ff[2][4][4], float* sred,
                                            int mbase, int nb, int g_, int tg){
  #pragma unroll
  for (int mi = 0; mi < 2; mi++)
    #pragma unroll
    for (int rr = 0; rr < 2; rr++){
      float s = 0.f, q = 0.f;
      #pragma unroll
      for (int j = 0; j < 4; j++){
        float v0 = ff[mi][j][rr*2+0], v1 = ff[mi][j][rr*2+1];
        s += v0 + v1; q += v0*v0 + v1*v1;
      }
      s += __shfl_xor_sync(0xffffffffu, s, 1);
      s += __shfl_xor_sync(0xffffffffu, s, 2);
      q += __shfl_xor_sync(0xffffffffu, q, 1);
      q += __shfl_xor_sync(0xffffffffu, q, 2);
      if (tg == 0){
        int row = mbase + mi*16 + g_ + rr*8;
        sred[row*8 + nb]     = s;
        sred[row*8 + 4 + nb] = q;
      }
    }
}
__device__ __forceinline__ void ln_finish(const float ff[2][4][4], const float* sred,
                                          float* act, const float* __restrict__ wg_g,
                                          const float* __restrict__ bg_g,
                                          int mbase, int nbase, int g_, int tg){
  float2 wj[4], bj[4];
  #pragma unroll
  for (int j = 0; j < 4; j++){
    wj[j] = *reinterpret_cast<const float2*>(wg_g + nbase + 8*j + 2*tg);
    bj[j] = *reinterpret_cast<const float2*>(bg_g + nbase + 8*j + 2*tg);
  }
  #pragma unroll
  for (int mi = 0; mi < 2; mi++)
    #pragma unroll
    for (int rr = 0; rr < 2; rr++){
      int row = mbase + mi*16 + g_ + rr*8;
      float4 s4 = *reinterpret_cast<const float4*>(sred + row*8);
      float4 q4 = *reinterpret_cast<const float4*>(sred + row*8 + 4);
      float s = (s4.x + s4.y) + (s4.z + s4.w);
      float q = (q4.x + q4.y) + (q4.z + q4.w);
      float m   = s * (1.f/NC);
      float var = q * (1.f/NC) - m*m;
      float rs  = rsqrtf(var + 1e-5f);
      #pragma unroll
      for (int j = 0; j < 4; j++){
        float2 o;
        o.x = tf32f((ff[mi][j][rr*2+0]-m)*rs*wj[j].x + bj[j].x);
        o.y = tf32f((ff[mi][j][rr*2+1]-m)*rs*wj[j].y + bj[j].y);
        *reinterpret_cast<float2*>(act + row*PA + nbase + 8*j + 2*tg) = o;
      }
    }
}

__global__ void __launch_bounds__(256, 3)
lane_fusion_kernel(Params P){
  extern __shared__ float smem[];
  float* act = smem + OFF_ACT;
  float* wt0 = smem + OFF_WU;
  float* wt1 = smem + OFF_WU + 4352;
  float* wc0 = smem + OFF_WU;
  float* wc1 = smem + OFF_WU + 4352;
  float* sg  = smem + OFF_SG;
  float* sred= smem + OFF_SRED;
  int*   sidx= (int*)(smem + OFF_SIDX);

  const int tid  = threadIdx.x;
  const int lane = tid & 31;
  const int warp = tid >> 5;
  const int g_   = lane >> 2;
  const int tg   = lane & 3;
  const int mbase = (warp & 1) * 32;
  const int nbase = (warp >> 1) * 32;
  const int nb    = warp >> 1;
  const int r    = blockIdx.x;
  const float* xr = P.x + (size_t)r * (NV*5);

  // ----- preprocess -----
  if (tid < NV){
    float x0 = xr[tid*5+0], x1 = xr[tid*5+1], hg = xr[tid*5+2];
    float x3 = xr[tid*5+3], x4 = xr[tid*5+4];
    float ch = cosf(hg), sh = sinf(hg);
    sg[tid*4+0] = x0; sg[tid*4+1] = x1; sg[tid*4+2] = ch; sg[tid*4+3] = sh;
    int tl = (int)x3; tl = tl < 0 ? 0 : (tl > N_TL-1 ? N_TL-1 : tl);
    int lt = (int)x4; lt = lt < 0 ? 0 : (lt > N_LT-1 ? N_LT-1 : lt);
    sidx[tid]      = tl;
    sidx[NV+tid]   = lt;
    sidx[2*NV+tid] = (x0==0.f && x1==0.f && ch==0.f && sh==0.f) ? 1 : 0;
  }
  if (tid < 5){
    float mid = xr[(NV/2)*5 + tid];
    float sc = (tid==3) ? (1.f/(N_TL-1)) : ((tid==4) ? (1.f/(N_LT-1)) : 1.f);
    P.pos_out[(size_t)r*5 + tid] = mid * sc;
  }
  __syncthreads();
  if (tid == 0){
    int mp = 1;
    for (int v = 0; v < NV; v++) mp &= sidx[2*NV+v];
    sidx[3*NV] = mp;
    P.mask_out[r] = mp ? 1.f : 0.f;
  }

  // ----- 1a: h1 = gelu(g @ ch1w + b) -> act rows 0..23 (20..23 zero), tf32
  {
    int c  = tid & 127;
    int hf = tid >> 7;
    float w0 = P.ch1w[0*NC + c], w1 = P.ch1w[1*NC + c];
    float w2 = P.ch1w[2*NC + c], w3 = P.ch1w[3*NC + c];
    float b  = P.ch1b[c];
    #pragma unroll
    for (int v = hf*10; v < hf*10 + 10; v++){
      float a = b + sg[v*4+0]*w0 + sg[v*4+1]*w1 + sg[v*4+2]*w2 + sg[v*4+3]*w3;
      act[v*PA + c] = tf32f(gelu_f(a));
    }
    if (hf == 0){
      #pragma unroll
      for (int v = NV; v < 24; v++) act[v*PA + c] = 0.f;
    }
  }
  cpa_tile(wc0, g_wc[0], tid);   // ch2w tile0 (pre-rounded)
  cpa_wait();
  __syncthreads();

  float ff[2][4][4];            // register-resident residual state tile

  // ----- 1b: f0 = h1 @ ch2w + b + tables -> act rows 32..55 (52..55 zero)
  {
    float acc[2][4][4]; zacc(acc);
    bool active = (mbase == 0);
    chan_gemm<true>(act, g_wc[0], nullptr, acc, wc0, wc1, mbase, nbase, g_, tg, tid, active);
    // wu free after final internal sync — stage token weights asynchronously
    cpa_wt(wt0, g_wt[0], tid);
    cpa_wt(wt1, g_wt[1], tid);
    if (active){
      #pragma unroll
      for (int mi = 0; mi < 2; mi++)
        #pragma unroll
        for (int rr = 0; rr < 2; rr++){
          int v = mi*16 + g_ + rr*8;
          if (v < NV){
            int tl = sidx[v], lt = sidx[NV+v];
            #pragma unroll
            for (int j = 0; j < 4; j++){
              int cn = nbase + 8*j + 2*tg;
              float2 b2 = *reinterpret_cast<const float2*>(P.ch2b + cn);
              float2 t2 = *reinterpret_cast<const float2*>(P.tl_table + tl*NC + cn);
              float2 l2 = *reinterpret_cast<const float2*>(P.lane_table + lt*NC + cn);
              float2 o;
              o.x = tf32f(acc[mi][j][rr*2+0] + b2.x + t2.x + l2.x);
              o.y = tf32f(acc[mi][j][rr*2+1] + b2.y + t2.y + l2.y);
              *reinterpret_cast<float2*>(act + (32+v)*PA + cn) = o;
            }
          } else if (v < 24){
            #pragma unroll
            for (int j = 0; j < 4; j++){
              int cn = nbase + 8*j + 2*tg;
              float2 z; z.x = 0.f; z.y = 0.f;
              *reinterpret_cast<float2*>(act + (32+v)*PA + cn) = z;
            }
          }
        }
    }
    cpa_wait();
  }
  __syncthreads();   // S1: f0 + wt ready

  // ----- token expansion -----
  {
    float acc[2][4][4]; zacc(acc);
    tok_mma<3>(act + 32*PA, wt0, acc, mbase, nbase, g_, tg);   // B = f0
    __syncthreads(); // T1: all f0 reads done
    #pragma unroll
    for (int mi = 0; mi < 2; mi++)
      #pragma unroll
      for (int rr = 0; rr < 2; rr++){
        int u = mbase + mi*16 + g_ + rr*8;
        float bb = P.tk1b[u];
        #pragma unroll
        for (int j = 0; j < 4; j++){
          int cn = nbase + 8*j + 2*tg;
          float2 o;
          o.x = tf32f(gelu_f(acc[mi][j][rr*2+0] + bb));
          o.y = tf32f(gelu_f(acc[mi][j][rr*2+1] + bb));
          *reinterpret_cast<float2*>(act + u*PA + cn) = o;     // z1
        }
      }
  }
  __syncthreads();   // T2: z1 ready
  {
    zacc(ff);
    tok_mma<8>(act, wt1, ff, mbase, nbase, g_, tg);            // f = z1 @ W2
    #pragma unroll
    for (int mi = 0; mi < 2; mi++)
      #pragma unroll
      for (int rr = 0; rr < 2; rr++){
        float bb = P.tk2b[mbase + mi*16 + g_ + rr*8];
        #pragma unroll
        for (int j = 0; j < 4; j++){
          ff[mi][j][rr*2+0] += bb;
          ff[mi][j][rr*2+1] += bb;
        }
      }
  }
  __syncthreads();   // T3: z1 reads done; act + wu free

  // ----- mixer blocks -----
  for (int d = 0; d < NDEPTH; d++){
    // stage token weights async + LN1 partials
    cpa_wt(wt0, g_wt[2+d], tid);
    cpa_wt(wt1, g_wt[5+d], tid);
    ln_partials(ff, sred, mbase, nb, g_, tg);
    cpa_wait();
    __syncthreads();  // A1
    ln_finish(ff, sred, act, P.bn1w + d*NC, P.bn1b + d*NC, mbase, nbase, g_, tg);
    __syncthreads();  // A2: y + wt ready

    // token mix 1
    {
      float acc[2][4][4]; zacc(acc);
      tok_mma<8>(act, wt0, acc, mbase, nbase, g_, tg);
      __syncthreads(); // B: y reads done
      #pragma unroll
      for (int mi = 0; mi < 2; mi++)
        #pragma unroll
        for (int rr = 0; rr < 2; rr++){
          int u = mbase + mi*16 + g_ + rr*8;
          float bb = P.bt1b[d*NT + u];
          #pragma unroll
          for (int j = 0; j < 4; j++){
            int cn = nbase + 8*j + 2*tg;
            float2 o;
            o.x = tf32f(gelu_f(acc[mi][j][rr*2+0] + bb));
            o.y = tf32f(gelu_f(acc[mi][j][rr*2+1] + bb));
            *reinterpret_cast<float2*>(act + u*PA + cn) = o;   // z
          }
        }
    }
    __syncthreads();  // C: z ready

    // token mix 2: accumulate directly into ff (residual free)
    tok_mma<8>(act, wt1, ff, mbase, nbase, g_, tg);
    #pragma unroll
    for (int mi = 0; mi < 2; mi++)
      #pragma unroll
      for (int rr = 0; rr < 2; rr++){
        float bb = P.bt2b[d*NT + mbase + mi*16 + g_ + rr*8];
        #pragma unroll
        for (int j = 0; j < 4; j++){
          ff[mi][j][rr*2+0] += bb;
          ff[mi][j][rr*2+1] += bb;
        }
      }
    __syncthreads();  // D: z reads done; act + wu free

    // LN2 partials + async prefetch bc1w tile0
    cpa_tile(wc0, g_wc[1+d], tid);
    ln_partials(ff, sred, mbase, nb, g_, tg);
    __syncthreads();  // E1
    ln_finish(ff, sred, act, P.bn2w + d*NC, P.bn2b + d*NC, mbase, nbase, g_, tg);
    cpa_wait();
    __syncthreads();  // E2: y2 + wc0 ready

    // channel mix C1 -> h
    {
      float acc[2][4][4]; zacc(acc);
      chan_gemm<true>(act, g_wc[1+d], g_wc[4+d], acc, wc0, wc1,
                      mbase, nbase, g_, tg, tid, true);
      #pragma unroll
      for (int j = 0; j < 4; j++){
        int cn = nbase + 8*j + 2*tg;
        float2 b2 = *reinterpret_cast<const float2*>(P.bc1b + d*NC + cn);
        #pragma unroll
        for (int mi = 0; mi < 2; mi++)
          #pragma unroll
          for (int rr = 0; rr < 2; rr++){
            int t = mbase + mi*16 + g_ + rr*8;
            float2 o;
            o.x = tf32f(gelu_f(acc[mi][j][rr*2+0] + b2.x));
            o.y = tf32f(gelu_f(acc[mi][j][rr*2+1] + b2.y));
            *reinterpret_cast<float2*>(act + t*PA + cn) = o;   // h
          }
      }
    }
    __syncthreads();  // G: h ready

    // channel mix C2: accumulate into ff
    chan_gemm<false>(act, g_wc[4+d], nullptr, ff, wc0, wc1,
                     mbase, nbase, g_, tg, tid, true);
    #pragma unroll
    for (int j = 0; j < 4; j++){
      int cn = nbase + 8*j + 2*tg;
      float2 b2 = *reinterpret_cast<const float2*>(P.bc2b + d*NC + cn);
      #pragma unroll
      for (int mi = 0; mi < 2; mi++)
        #pragma unroll
        for (int rr = 0; rr < 2; rr++){
          ff[mi][j][rr*2+0] += b2.x;
          ff[mi][j][rr*2+1] += b2.y;
        }
    }
    __syncthreads();  // H: h reads done; act/sred/wu free
  }

  // ----- epilogue: token mean from ff, LN, emb MLP -----
  {
    float cs[4][2];
    #pragma unroll
    for (int j = 0; j < 4; j++)
      #pragma unroll
      for (int q = 0; q < 2; q++)
        cs[j][q] = (ff[0][j][q] + ff[0][j][2+q]) + (ff[1][j][q] + ff[1][j][2+q]);
    #pragma unroll
    for (int off = 4; off <= 16; off <<= 1)
      #pragma unroll
      for (int j = 0; j < 4; j++)
        #pragma unroll
        for (int q = 0; q < 2; q++)
          cs[j][q] += __shfl_xor_sync(0xffffffffu, cs[j][q], off);
    if (g_ == 0){
      #pragma unroll
      for (int j = 0; j < 4; j++){
        float2 o; o.x = cs[j][0]; o.y = cs[j][1];
        *reinterpret_cast<float2*>(act + (warp & 1)*128 + nbase + 8*j + 2*tg) = o;
      }
    }
  }
  __syncthreads();
  float fm = 0.f;
  if (tid < NC){
    fm = (act[tid] + act[128 + tid]) * (1.f/NT);
    float s = fm, q = fm*fm;
    #pragma unroll
    for (int o = 16; o > 0; o >>= 1){
      s += __shfl_xor_sync(0xffffffffu, s, o);
      q += __shfl_xor_sync(0xffffffffu, q, o);
    }
    if (lane == 0){ sred[warp] = s; sred[4+warp] = q; }
  }
  __syncthreads();
  if (tid < NC){
    float s = sred[0]+sred[1]+sred[2]+sred[3];
    float q = sred[4]+sred[5]+sred[6]+sred[7];
    float m  = s * (1.f/NC);
    float var = q * (1.f/NC) - m*m;
    float rs = rsqrtf(var + 1e-5f);
    act[256 + tid] = (fm - m)*rs*P.nw[tid] + P.nb[tid];
  }
  __syncthreads();
  if (tid < NH){
    float a = P.e1b[tid];
    #pragma unroll 8
    for (int c = 0; c < NC; c++) a += act[256 + c] * P.e1w[c*NH + tid];
    act[512 + tid] = gelu_f(a);
  }
  __syncthreads();
  if (tid < NH){
    float o = P.e2b[tid];
    #pragma unroll 8
    for (int j = 0; j < NH; j++) o += act[512 + j] * P.e2w[j*NH + tid];
    float valid = sidx[3*NV] ? 0.f : 1.f;
    P.out[(size_t)r * NH + tid] = o * valid;
  }
}

extern "C" void kernel_launch(void* const* d_in, const int* in_sizes, int n_in,
                              void* d_out, int out_size){
  (void)in_sizes; (void)n_in; (void)out_size;
  Params P;
  P.x         = (const float*)d_in[0];
  P.tl_table  = (const float*)d_in[1];
  P.lane_table= (const float*)d_in[2];
  P.ch1w = (const float*)d_in[3];  P.ch1b = (const float*)d_in[4];
  P.ch2w = (const float*)d_in[5];  P.ch2b = (const float*)d_in[6];
  P.tk1w = (const float*)d_in[7];  P.tk1b = (const float*)d_in[8];
  P.tk2w = (const float*)d_in[9];  P.tk2b = (const float*)d_in[10];
  P.bn1w = (const float*)d_in[11]; P.bn1b = (const float*)d_in[12];
  P.bt1w = (const float*)d_in[13]; P.bt1b = (const float*)d_in[14];
  P.bt2w = (const float*)d_in[15]; P.bt2b = (const float*)d_in[16];
  P.bn2w = (const float*)d_in[17]; P.bn2b = (const float*)d_in[18];
  P.bc1w = (const float*)d_in[19]; P.bc1b = (const float*)d_in[20];
  P.bc2w = (const float*)d_in[21]; P.bc2b = (const float*)d_in[22];
  P.nw   = (const float*)d_in[23]; P.nb   = (const float*)d_in[24];
  P.e1w  = (const float*)d_in[25]; P.e1b  = (const float*)d_in[26];
  P.e2w  = (const float*)d_in[27]; P.e2b  = (const float*)d_in[28];

  const int NRows = 8192;
  float* ob = (float*)d_out;
  P.out      = ob;
  P.mask_out = ob + (size_t)NRows*NH;
  P.pos_out  = ob + (size_t)NRows*NH + NRows;

  prep_kernel<<<(PREP_TOT + 255)/256, 256>>>(P);

  cudaFuncSetAttribute(lane_fusion_kernel,
                       cudaFuncAttributeMaxDynamicSharedMemorySize, SMEM_BYTES);
  lane_fusion_kernel<<<NRows, 256, SMEM_BYTES>>>(P);
}